// round 7
// baseline (speedup 1.0000x reference)
#include <cuda_runtime.h>
#include <cuda_bf16.h>
#include <cstdint>

#define HH 512
#define WW 512
#define NPIX (HH * WW)
#define NITER 100
#define NBLK 128
#define NTHR 1024
#define STRIDE (NBLK * NTHR)   // 131072
#define PPT 2                  // exact fit: 128*1024*2 == 262144
#define IBAR NITER             // init-barrier counter slot

// Replay-safe persistent state:
//  - g_arrive[s]: monotonic arrival counters. Base read at entry from slot
//    NITER-1 (first incremented only after every block has entered).
//  - g_acc[c][it]: 4 accumulator arrays, each NITER*8B, on DIFFERENT cache
//    lines (and thus usually different LTS slices) so the 128 per-slot REDs
//    serialize in parallel across slices. Zeroed by block 0 pre-init-barrier.
//  - g_pkt[b]: per-block 128B mailbox. Words [0..3]={ver,sc,r,tx},
//    [4..7]={ver,ty,0,0} (both in sector 0), word [8]=init flag. Version
//    words are monotonic; the one-outstanding-version argument (a releaser
//    for it+1 cannot exist until every block consumed it) makes the
//    two-16B-store packet tear-safe under the dual version check.
__device__ unsigned g_arrive[NITER + 1];
__device__ double g_acc[4][NITER];
__device__ __align__(128) unsigned g_pkt[NBLK][32];   // 128B per block

__device__ __forceinline__ unsigned ld_acquire(const unsigned* p) {
    unsigned v;
    asm volatile("ld.acquire.gpu.global.u32 %0, [%1];" : "=r"(v) : "l"(p) : "memory");
    return v;
}
__device__ __forceinline__ void st_release(unsigned* p, unsigned v) {
    asm volatile("st.release.gpu.global.u32 [%0], %1;" :: "l"(p), "r"(v) : "memory");
}
__device__ __forceinline__ unsigned atom_add_acqrel(unsigned* p, unsigned v) {
    unsigned o;
    asm volatile("atom.acq_rel.gpu.global.add.u32 %0, [%1], %2;"
                 : "=r"(o) : "l"(p), "r"(v) : "memory");
    return o;
}
__device__ __forceinline__ uint4 ldcg128(const unsigned* p) {
    uint4 v;
    asm volatile("ld.global.cg.v4.u32 {%0,%1,%2,%3}, [%4];"
                 : "=r"(v.x), "=r"(v.y), "=r"(v.z), "=r"(v.w) : "l"(p) : "memory");
    return v;
}
__device__ __forceinline__ void stcg128(unsigned* p, uint4 v) {
    asm volatile("st.global.cg.v4.u32 [%0], {%1,%2,%3,%4};"
                 :: "l"(p), "r"(v.x), "r"(v.y), "r"(v.z), "r"(v.w) : "memory");
}
__device__ __forceinline__ double ldcg64(const double* p) {
    double v;
    asm volatile("ld.global.cg.f64 %0, [%1];" : "=d"(v) : "l"(p) : "memory");
    return v;
}

__global__ void __launch_bounds__(NTHR, 1)
reg_kernel(const float* __restrict__ mov, const float* __restrict__ fix,
           const float* __restrict__ scale0, const float* __restrict__ rot0,
           const float* __restrict__ trans0, float* __restrict__ out) {
    __shared__ float shp[4];      // Ap, Bp, TX, TY for this iteration
    __shared__ float red[32][4];

    const int tid  = threadIdx.x;
    const int bid  = blockIdx.x;
    const int gid  = bid * NTHR + tid;
    const int lane = tid & 31;
    const int wid  = tid >> 5;

    // Entry bases (read before any arrival; monotonicity argument above).
    unsigned base_arr = 0, base_ver = 0, base_ifl = 0;
    float sc = 0.f, r = 0.f, tx = 0.f, ty = 0.f;
    if (tid < 32) {
        base_ver = *(volatile unsigned*)&g_pkt[bid][0];
        base_ifl = *(volatile unsigned*)&g_pkt[bid][8];
    }
    if (tid == 0) {
        base_arr = *(volatile unsigned*)&g_arrive[NITER - 1];
        sc = scale0[0]; r = rot0[0]; tx = trans0[0]; ty = trans0[1];
        float cc = cosf(r), ss = sinf(r);
        shp[0] = 256.0f * sc * cc; shp[1] = 256.0f * sc * ss;
        shp[2] = 256.0f * tx + 255.5f; shp[3] = 256.0f * ty + 255.5f;
    }

    // Iteration-invariant per-pixel data in registers.
    float pxj[PPT], pyv[PPT], pfx[PPT];
#pragma unroll
    for (int k = 0; k < PPT; k++) {
        int p = gid + k * STRIDE;
        int i = p >> 9, j = p & 511;
        pxj[k] = ((float)j + 0.5f) * (2.0f / 512.0f) - 1.0f;
        pyv[k] = ((float)i + 0.5f) * (2.0f / 512.0f) - 1.0f;
        pfx[k] = fix[p];
    }

    // ── Init barrier: block 0 zeroes accumulators; release via per-block
    //    st.release/ld.acquire flags on each mailbox line.
    if (bid == 0 && tid < 4 * NITER)
        ((double*)g_acc)[tid] = 0.0;
    __syncthreads();
    if (tid < 32) {
        unsigned islast = 0;
        if (tid == 0) {
            unsigned old = atom_add_acqrel(&g_arrive[IBAR], 1u);
            islast = (old - base_arr == (unsigned)(NBLK - 1)) ? 1u : 0u;
        }
        __syncwarp();
        islast = __shfl_sync(0xFFFFFFFFu, islast, 0);
        if (islast) {
#pragma unroll
            for (int k = 0; k < 4; k++)
                st_release(&g_pkt[lane * 4 + k][8], base_ifl + 1u);
        } else if (tid == 0) {
            while (ld_acquire(&g_pkt[bid][8]) - base_ifl < 1u) { }
        }
    }
    __syncthreads();

    for (int it = 0; it < NITER; it++) {
        const float Ap = shp[0], Bp = shp[1], TX = shp[2], TY = shp[3];

        float a0 = 0.f, a1 = 0.f, a2 = 0.f, a3 = 0.f;
#pragma unroll
        for (int k = 0; k < PPT; k++) {
            const float xj = pxj[k], yv = pyv[k];
            float ix = fmaf(Ap, xj, fmaf(-Bp, yv, TX));
            float iy = fmaf(Bp, xj, fmaf(Ap, yv, TY));
            float up = ix - TX;           // = 256*sc*(c*xj - s*yv)
            float vp = iy - TY;           // = 256*sc*(s*xj + c*yv)
            int ix0 = __float2int_rd(ix);
            int iy0 = __float2int_rd(iy);
            float wx1 = ix - (float)ix0;
            float wy1 = iy - (float)iy0;
            bool px0 = (unsigned)ix0 < 512u;
            bool px1 = (unsigned)(ix0 + 1) < 512u;
            bool py0 = (unsigned)iy0 < 512u;
            bool py1 = (unsigned)(iy0 + 1) < 512u;
            int a00 = iy0 * 512 + ix0;
            float v00 = (px0 && py0) ? __ldg(mov + a00)       : 0.0f;
            float v01 = (px1 && py0) ? __ldg(mov + a00 + 1)   : 0.0f;
            float v10 = (px0 && py1) ? __ldg(mov + a00 + 512) : 0.0f;
            float v11 = (px1 && py1) ? __ldg(mov + a00 + 513) : 0.0f;
            float d0 = v01 - v00;
            float d1 = v11 - v10;
            float m0 = fmaf(wx1, d0, v00);
            float m1 = fmaf(wx1, d1, v10);
            float dtdx = fmaf(wy1, d1 - d0, d0);
            float dtdy = m1 - m0;
            float tr = fmaf(wy1, dtdy, m0);
            float resid = tr - pfx[k];
            float rx = resid * dtdx;
            float ry = resid * dtdy;
            a2 += rx;
            a3 += ry;
            a0 = fmaf(rx, up, a0);
            a0 = fmaf(ry, vp, a0);
            a1 = fmaf(ry, up, a1);
            a1 = fmaf(-rx, vp, a1);
        }

#pragma unroll
        for (int off = 16; off > 0; off >>= 1) {
            a0 += __shfl_down_sync(0xFFFFFFFFu, a0, off);
            a1 += __shfl_down_sync(0xFFFFFFFFu, a1, off);
            a2 += __shfl_down_sync(0xFFFFFFFFu, a2, off);
            a3 += __shfl_down_sync(0xFFFFFFFFu, a3, off);
        }
        if (lane == 0) {
            red[wid][0] = a0; red[wid][1] = a1; red[wid][2] = a2; red[wid][3] = a3;
        }
        __syncthreads();
        if (tid < 32) {
            float4 v = *(const float4*)red[tid];
            float b0 = v.x, b1 = v.y, b2 = v.z, b3 = v.w;
#pragma unroll
            for (int off = 16; off > 0; off >>= 1) {
                b0 += __shfl_down_sync(0xFFFFFFFFu, b0, off);
                b1 += __shfl_down_sync(0xFFFFFFFFu, b1, off);
                b2 += __shfl_down_sync(0xFFFFFFFFu, b2, off);
                b3 += __shfl_down_sync(0xFFFFFFFFu, b3, off);
            }
            unsigned islast = 0;
            if (tid == 0) {
                // relaxed fp64 REDs to 4 separate lines/slices; ordered by
                // the acq_rel arrival below
                atomicAdd(&g_acc[0][it], (double)b0);
                atomicAdd(&g_acc[1][it], (double)b1);
                atomicAdd(&g_acc[2][it], (double)b2);
                atomicAdd(&g_acc[3][it], (double)b3);
                unsigned old = atom_add_acqrel(&g_arrive[it], 1u);
                islast = (old - base_arr == (unsigned)(NBLK - 1)) ? 1u : 0u;
            }
            __syncwarp();
            islast = __shfl_sync(0xFFFFFFFFu, islast, 0);
            const unsigned need = (unsigned)(it + 1);
            if (islast) {
                unsigned w1 = 0, w2 = 0, w3 = 0, w4 = 0;
                if (tid == 0) {
                    // acquire orders these after all blocks' REDs; 4 parallel loads
                    double s0 = ldcg64(&g_acc[0][it]);
                    double s1 = ldcg64(&g_acc[1][it]);
                    double s2 = ldcg64(&g_acc[2][it]);
                    double s3 = ldcg64(&g_acc[3][it]);
                    float gs  = (float)(s0 * (1.0 / 131072.0)) / sc;
                    float gr  = (float)(s1 * (1.0 / 131072.0));
                    float gtx = (float)(s2 * (1.0 / 512.0));
                    float gty = (float)(s3 * (1.0 / 512.0));
                    sc -= gs; r -= gr; tx -= gtx; ty -= gty;  // LR = 1
                    w1 = __float_as_uint(sc); w2 = __float_as_uint(r);
                    w3 = __float_as_uint(tx); w4 = __float_as_uint(ty);
                }
                __syncwarp();
                w1 = __shfl_sync(0xFFFFFFFFu, w1, 0);
                w2 = __shfl_sync(0xFFFFFFFFu, w2, 0);
                w3 = __shfl_sync(0xFFFFFFFFu, w3, 0);
                w4 = __shfl_sync(0xFFFFFFFFu, w4, 0);
                const unsigned ver = base_ver + need;
                uint4 k0 = make_uint4(ver, w1, w2, w3);
                uint4 k1 = make_uint4(ver, w4, 0u, 0u);
#pragma unroll
                for (int k = 0; k < 4; k++) {
                    stcg128(&g_pkt[lane * 4 + k][0], k0);
                    stcg128(&g_pkt[lane * 4 + k][4], k1);
                }
            } else if (tid == 0) {
                // A/B pipelined spin on our private line: next probe is in
                // flight before the current one is checked.
                uint4 q0, q1;
                uint4 A0 = ldcg128(&g_pkt[bid][0]);
                uint4 A1 = ldcg128(&g_pkt[bid][4]);
                for (;;) {
                    uint4 B0 = ldcg128(&g_pkt[bid][0]);
                    uint4 B1 = ldcg128(&g_pkt[bid][4]);
                    if (A0.x - base_ver >= need && A1.x - base_ver >= need) {
                        q0 = A0; q1 = A1; break;
                    }
                    A0 = ldcg128(&g_pkt[bid][0]);
                    A1 = ldcg128(&g_pkt[bid][4]);
                    if (B0.x - base_ver >= need && B1.x - base_ver >= need) {
                        q0 = B0; q1 = B1; break;
                    }
                }
                sc = __uint_as_float(q0.y); r  = __uint_as_float(q0.z);
                tx = __uint_as_float(q0.w); ty = __uint_as_float(q1.y);
            }
            if (tid == 0) {
                float cc = cosf(r), ss = sinf(r);
                shp[0] = 256.0f * sc * cc; shp[1] = 256.0f * sc * ss;
                shp[2] = 256.0f * tx + 255.5f; shp[3] = 256.0f * ty + 255.5f;
            }
        }
        __syncthreads();
    }

    // Final transform with post-100-step params.
    {
        const float Ap = shp[0], Bp = shp[1], TX = shp[2], TY = shp[3];
#pragma unroll
        for (int k = 0; k < PPT; k++) {
            int p = gid + k * STRIDE;
            const float xj = pxj[k], yv = pyv[k];
            float ix = fmaf(Ap, xj, fmaf(-Bp, yv, TX));
            float iy = fmaf(Bp, xj, fmaf(Ap, yv, TY));
            int ix0 = __float2int_rd(ix);
            int iy0 = __float2int_rd(iy);
            float wx1 = ix - (float)ix0;
            float wy1 = iy - (float)iy0;
            bool px0 = (unsigned)ix0 < 512u;
            bool px1 = (unsigned)(ix0 + 1) < 512u;
            bool py0 = (unsigned)iy0 < 512u;
            bool py1 = (unsigned)(iy0 + 1) < 512u;
            int a00 = iy0 * 512 + ix0;
            float v00 = (px0 && py0) ? __ldg(mov + a00)       : 0.0f;
            float v01 = (px1 && py0) ? __ldg(mov + a00 + 1)   : 0.0f;
            float v10 = (px0 && py1) ? __ldg(mov + a00 + 512) : 0.0f;
            float v11 = (px1 && py1) ? __ldg(mov + a00 + 513) : 0.0f;
            float d0 = v01 - v00;
            float d1 = v11 - v10;
            float m0 = fmaf(wx1, d0, v00);
            float m1 = fmaf(wx1, d1, v10);
            float tr = fmaf(wy1, m1 - m0, m0);
            out[p] = tr;
        }
    }
}

extern "C" void kernel_launch(void* const* d_in, const int* in_sizes, int n_in,
                              void* d_out, int out_size) {
    const float* mov   = (const float*)d_in[0];
    const float* fix   = (const float*)d_in[1];
    const float* scale = (const float*)d_in[2];
    const float* rot   = (const float*)d_in[3];
    const float* trans = (const float*)d_in[4];
    float* out = (float*)d_out;
    reg_kernel<<<NBLK, NTHR>>>(mov, fix, scale, rot, trans, out);
}

// round 8
// speedup vs baseline: 1.5010x; 1.5010x over previous
#include <cuda_runtime.h>
#include <cuda_bf16.h>
#include <cstdint>

#define HH 512
#define WW 512
#define NPIX (HH * WW)
#define NITER 100
#define NBLK 128
#define NTHR 1024
#define STRIDE (NBLK * NTHR)   // 131072
#define PPT 2                  // exact fit: 128*1024*2 == 262144
#define IBAR NITER             // init-barrier counter slot

// Replay-safe persistent state:
//  - g_arrive[s]: monotonic arrival counters. Base read at entry from slot
//    NITER-1 (first incremented only after every block has entered).
//  - g_acc[it]: one 32B sector per iteration; zeroed by block 0 before the
//    init barrier each launch; relaxed fp64 REDs ordered by the acq_rel
//    arrival counter.
//  - g_pkt[b]: per-block 128B mailbox. Words [0..3]={ver,sc,r,tx},
//    [4..7]={ver,ty,0,0}, word [8]=init flag. Version words monotonic; only
//    one version can be outstanding (a releaser for it+1 cannot exist until
//    every block consumed it), so the two-16B-store packet is tear-safe under
//    the dual version check.
__device__ unsigned g_arrive[NITER + 1];
__device__ double g_acc[NITER][4];
__device__ __align__(128) unsigned g_pkt[NBLK][32];   // 128B per block

__device__ __forceinline__ unsigned ld_acquire(const unsigned* p) {
    unsigned v;
    asm volatile("ld.acquire.gpu.global.u32 %0, [%1];" : "=r"(v) : "l"(p) : "memory");
    return v;
}
__device__ __forceinline__ void st_release(unsigned* p, unsigned v) {
    asm volatile("st.release.gpu.global.u32 [%0], %1;" :: "l"(p), "r"(v) : "memory");
}
__device__ __forceinline__ unsigned atom_add_acqrel(unsigned* p, unsigned v) {
    unsigned o;
    asm volatile("atom.acq_rel.gpu.global.add.u32 %0, [%1], %2;"
                 : "=r"(o) : "l"(p), "r"(v) : "memory");
    return o;
}
__device__ __forceinline__ uint4 ldcg128(const unsigned* p) {
    uint4 v;
    asm volatile("ld.global.cg.v4.u32 {%0,%1,%2,%3}, [%4];"
                 : "=r"(v.x), "=r"(v.y), "=r"(v.z), "=r"(v.w) : "l"(p) : "memory");
    return v;
}
__device__ __forceinline__ void stcg128(unsigned* p, uint4 v) {
    asm volatile("st.global.cg.v4.u32 [%0], {%1,%2,%3,%4};"
                 :: "l"(p), "r"(v.x), "r"(v.y), "r"(v.z), "r"(v.w) : "memory");
}

__global__ void __launch_bounds__(NTHR, 1)
reg_kernel(const float* __restrict__ mov, const float* __restrict__ fix,
           const float* __restrict__ scale0, const float* __restrict__ rot0,
           const float* __restrict__ trans0, float* __restrict__ out) {
    __shared__ float shp[4];      // Ap, Bp, TX, TY for this iteration
    __shared__ float red[32][4];

    const int tid  = threadIdx.x;
    const int bid  = blockIdx.x;
    const int gid  = bid * NTHR + tid;
    const int lane = tid & 31;
    const int wid  = tid >> 5;

    // Entry bases (read before any arrival; monotonicity argument above).
    unsigned base_arr = 0, base_ver = 0, base_ifl = 0;
    float sc = 0.f, r = 0.f, tx = 0.f, ty = 0.f, invsc = 0.f;
    if (tid < 32) {
        base_ver = *(volatile unsigned*)&g_pkt[bid][0];
        base_ifl = *(volatile unsigned*)&g_pkt[bid][8];
    }
    if (tid == 0) {
        base_arr = *(volatile unsigned*)&g_arrive[NITER - 1];
        sc = scale0[0]; r = rot0[0]; tx = trans0[0]; ty = trans0[1];
        invsc = 1.0f / sc;   // off critical path: computed at init / iter tail
        float cc = cosf(r), ss = sinf(r);
        shp[0] = 256.0f * sc * cc; shp[1] = 256.0f * sc * ss;
        shp[2] = 256.0f * tx + 255.5f; shp[3] = 256.0f * ty + 255.5f;
    }

    // Iteration-invariant per-pixel data in registers.
    float pxj[PPT], pyv[PPT], pfx[PPT];
#pragma unroll
    for (int k = 0; k < PPT; k++) {
        int p = gid + k * STRIDE;
        int i = p >> 9, j = p & 511;
        pxj[k] = ((float)j + 0.5f) * (2.0f / 512.0f) - 1.0f;
        pyv[k] = ((float)i + 0.5f) * (2.0f / 512.0f) - 1.0f;
        pfx[k] = fix[p];
    }

    // ── Init barrier: block 0 zeroes accumulators; release via per-block
    //    st.release/ld.acquire flags on each mailbox line.
    if (bid == 0 && tid < NITER * 4)
        ((double*)g_acc)[tid] = 0.0;
    __syncthreads();
    if (tid < 32) {
        unsigned islast = 0;
        if (tid == 0) {
            unsigned old = atom_add_acqrel(&g_arrive[IBAR], 1u);
            islast = (old - base_arr == (unsigned)(NBLK - 1)) ? 1u : 0u;
        }
        __syncwarp();
        islast = __shfl_sync(0xFFFFFFFFu, islast, 0);
        if (islast) {
#pragma unroll
            for (int k = 0; k < 4; k++)
                st_release(&g_pkt[lane * 4 + k][8], base_ifl + 1u);
        } else if (tid == 0) {
            while (ld_acquire(&g_pkt[bid][8]) - base_ifl < 1u) { }
        }
    }
    __syncthreads();

    for (int it = 0; it < NITER; it++) {
        const float Ap = shp[0], Bp = shp[1], TX = shp[2], TY = shp[3];

        float a0 = 0.f, a1 = 0.f, a2 = 0.f, a3 = 0.f;
#pragma unroll
        for (int k = 0; k < PPT; k++) {
            const float xj = pxj[k], yv = pyv[k];
            float ix = fmaf(Ap, xj, fmaf(-Bp, yv, TX));
            float iy = fmaf(Bp, xj, fmaf(Ap, yv, TY));
            float up = ix - TX;           // = 256*sc*(c*xj - s*yv)
            float vp = iy - TY;           // = 256*sc*(s*xj + c*yv)
            int ix0 = __float2int_rd(ix);
            int iy0 = __float2int_rd(iy);
            float wx1 = ix - (float)ix0;
            float wy1 = iy - (float)iy0;
            bool px0 = (unsigned)ix0 < 512u;
            bool px1 = (unsigned)(ix0 + 1) < 512u;
            bool py0 = (unsigned)iy0 < 512u;
            bool py1 = (unsigned)(iy0 + 1) < 512u;
            int a00 = iy0 * 512 + ix0;
            float v00 = (px0 && py0) ? __ldg(mov + a00)       : 0.0f;
            float v01 = (px1 && py0) ? __ldg(mov + a00 + 1)   : 0.0f;
            float v10 = (px0 && py1) ? __ldg(mov + a00 + 512) : 0.0f;
            float v11 = (px1 && py1) ? __ldg(mov + a00 + 513) : 0.0f;
            float d0 = v01 - v00;
            float d1 = v11 - v10;
            float m0 = fmaf(wx1, d0, v00);
            float m1 = fmaf(wx1, d1, v10);
            float dtdx = fmaf(wy1, d1 - d0, d0);
            float dtdy = m1 - m0;
            float tr = fmaf(wy1, dtdy, m0);
            float resid = tr - pfx[k];
            float rx = resid * dtdx;
            float ry = resid * dtdy;
            a2 += rx;
            a3 += ry;
            a0 = fmaf(rx, up, a0);
            a0 = fmaf(ry, vp, a0);
            a1 = fmaf(ry, up, a1);
            a1 = fmaf(-rx, vp, a1);
        }

#pragma unroll
        for (int off = 16; off > 0; off >>= 1) {
            a0 += __shfl_down_sync(0xFFFFFFFFu, a0, off);
            a1 += __shfl_down_sync(0xFFFFFFFFu, a1, off);
            a2 += __shfl_down_sync(0xFFFFFFFFu, a2, off);
            a3 += __shfl_down_sync(0xFFFFFFFFu, a3, off);
        }
        if (lane == 0) {
            red[wid][0] = a0; red[wid][1] = a1; red[wid][2] = a2; red[wid][3] = a3;
        }
        __syncthreads();
        if (tid < 32) {
            float4 v = *(const float4*)red[tid];
            float b0 = v.x, b1 = v.y, b2 = v.z, b3 = v.w;
#pragma unroll
            for (int off = 16; off > 0; off >>= 1) {
                b0 += __shfl_down_sync(0xFFFFFFFFu, b0, off);
                b1 += __shfl_down_sync(0xFFFFFFFFu, b1, off);
                b2 += __shfl_down_sync(0xFFFFFFFFu, b2, off);
                b3 += __shfl_down_sync(0xFFFFFFFFu, b3, off);
            }
            unsigned islast = 0;
            if (tid == 0) {
                // relaxed fp64 REDs; ordered by the acq_rel arrival below
                atomicAdd(&g_acc[it][0], (double)b0);
                atomicAdd(&g_acc[it][1], (double)b1);
                atomicAdd(&g_acc[it][2], (double)b2);
                atomicAdd(&g_acc[it][3], (double)b3);
                unsigned old = atom_add_acqrel(&g_arrive[it], 1u);
                islast = (old - base_arr == (unsigned)(NBLK - 1)) ? 1u : 0u;
            }
            __syncwarp();
            islast = __shfl_sync(0xFFFFFFFFu, islast, 0);
            const unsigned need = (unsigned)(it + 1);
            if (islast) {
                unsigned w1 = 0, w2 = 0, w3 = 0, w4 = 0;
                if (tid == 0) {
                    // acquire (in acq_rel) orders these loads after all REDs
                    double2 sA = __ldcg((const double2*)&g_acc[it][0]);
                    double2 sB = __ldcg((const double2*)&g_acc[it][2]);
                    float gs  = (float)(sA.x * (1.0 / 131072.0)) * invsc;
                    float gr  = (float)(sA.y * (1.0 / 131072.0));
                    float gtx = (float)(sB.x * (1.0 / 512.0));
                    float gty = (float)(sB.y * (1.0 / 512.0));
                    sc -= gs; r -= gr; tx -= gtx; ty -= gty;  // LR = 1
                    w1 = __float_as_uint(sc); w2 = __float_as_uint(r);
                    w3 = __float_as_uint(tx); w4 = __float_as_uint(ty);
                }
                __syncwarp();
                w1 = __shfl_sync(0xFFFFFFFFu, w1, 0);
                w2 = __shfl_sync(0xFFFFFFFFu, w2, 0);
                w3 = __shfl_sync(0xFFFFFFFFu, w3, 0);
                w4 = __shfl_sync(0xFFFFFFFFu, w4, 0);
                const unsigned ver = base_ver + need;
                uint4 k0 = make_uint4(ver, w1, w2, w3);
                uint4 k1 = make_uint4(ver, w4, 0u, 0u);
#pragma unroll
                for (int k = 0; k < 4; k++) {
                    stcg128(&g_pkt[lane * 4 + k][0], k0);
                    stcg128(&g_pkt[lane * 4 + k][4], k1);
                }
            } else if (tid == 0) {
                // dependent-load spin on our private mailbox line; the params
                // ride in the same 16B sector as the version word
                uint4 q0, q1;
                do {
                    q0 = ldcg128(&g_pkt[bid][0]);
                    q1 = ldcg128(&g_pkt[bid][4]);
                } while (q0.x - base_ver < need || q1.x - base_ver < need);
                sc = __uint_as_float(q0.y); r  = __uint_as_float(q0.z);
                tx = __uint_as_float(q0.w); ty = __uint_as_float(q1.y);
            }
            if (tid == 0) {
                // iteration tail (parallel across blocks, off the serial chain)
                invsc = 1.0f / sc;
                float cc = cosf(r), ss = sinf(r);
                shp[0] = 256.0f * sc * cc; shp[1] = 256.0f * sc * ss;
                shp[2] = 256.0f * tx + 255.5f; shp[3] = 256.0f * ty + 255.5f;
            }
        }
        __syncthreads();
    }

    // Final transform with post-100-step params.
    {
        const float Ap = shp[0], Bp = shp[1], TX = shp[2], TY = shp[3];
#pragma unroll
        for (int k = 0; k < PPT; k++) {
            int p = gid + k * STRIDE;
            const float xj = pxj[k], yv = pyv[k];
            float ix = fmaf(Ap, xj, fmaf(-Bp, yv, TX));
            float iy = fmaf(Bp, xj, fmaf(Ap, yv, TY));
            int ix0 = __float2int_rd(ix);
            int iy0 = __float2int_rd(iy);
            float wx1 = ix - (float)ix0;
            float wy1 = iy - (float)iy0;
            bool px0 = (unsigned)ix0 < 512u;
            bool px1 = (unsigned)(ix0 + 1) < 512u;
            bool py0 = (unsigned)iy0 < 512u;
            bool py1 = (unsigned)(iy0 + 1) < 512u;
            int a00 = iy0 * 512 + ix0;
            float v00 = (px0 && py0) ? __ldg(mov + a00)       : 0.0f;
            float v01 = (px1 && py0) ? __ldg(mov + a00 + 1)   : 0.0f;
            float v10 = (px0 && py1) ? __ldg(mov + a00 + 512) : 0.0f;
            float v11 = (px1 && py1) ? __ldg(mov + a00 + 513) : 0.0f;
            float d0 = v01 - v00;
            float d1 = v11 - v10;
            float m0 = fmaf(wx1, d0, v00);
            float m1 = fmaf(wx1, d1, v10);
            float tr = fmaf(wy1, m1 - m0, m0);
            out[p] = tr;
        }
    }
}

extern "C" void kernel_launch(void* const* d_in, const int* in_sizes, int n_in,
                              void* d_out, int out_size) {
    const float* mov   = (const float*)d_in[0];
    const float* fix   = (const float*)d_in[1];
    const float* scale = (const float*)d_in[2];
    const float* rot   = (const float*)d_in[3];
    const float* trans = (const float*)d_in[4];
    float* out = (float*)d_out;
    reg_kernel<<<NBLK, NTHR>>>(mov, fix, scale, rot, trans, out);
}